// round 2
// baseline (speedup 1.0000x reference)
#include <cuda_runtime.h>
#include <cuda_bf16.h>
#include <cstdint>
#include <math.h>

#define N_IN   8192
#define N_MC   32768
#define K_TOP  656
#define MASK_WORDS (N_IN / 32)          // 256

__device__ uint32_t g_mask[MASK_WORDS];
__device__ float    g_overlap[N_MC];

// ---------------------------------------------------------------------------
// Kernel 0: pack I (float32 0.0/1.0) into a bitmask
// ---------------------------------------------------------------------------
__global__ void pack_mask_kernel(const float* __restrict__ I) {
    int i = blockIdx.x * blockDim.x + threadIdx.x;   // 8192 threads
    bool b = (I[i] != 0.0f);
    unsigned ball = __ballot_sync(0xffffffffu, b);
    if ((i & 31) == 0) g_mask[i >> 5] = ball;
}

// ---------------------------------------------------------------------------
// Kernel 1: overlap_eff[row] = exp(na-dc) * popcount((perm_row >= 0.5) & I)
// One warp per row. float4 coalesced streaming of the 1.07 GB matrix.
// ---------------------------------------------------------------------------
__global__ __launch_bounds__(256) void overlap_kernel(
    const float* __restrict__ perm,
    const float* __restrict__ duty,
    const float* __restrict__ navg)
{
    __shared__ uint32_t smask[MASK_WORDS];
    int t = threadIdx.x;
    if (t < MASK_WORDS) smask[t] = g_mask[t];
    __syncthreads();

    int warp = t >> 5;
    int lane = t & 31;
    int row  = blockIdx.x * 8 + warp;

    const float4* p = reinterpret_cast<const float4*>(perm + (size_t)row * N_IN);

    int cnt = 0;
    // 8192 floats = 2048 float4 per row; 64 float4 per lane
    #pragma unroll 8
    for (int it = 0; it < 64; ++it) {
        int c4 = it * 32 + lane;                 // float4 index within row
        float4 v = __ldg(&p[c4]);
        int c = c4 * 4;                          // column of v.x
        uint32_t m = smask[c >> 5] >> (c & 31);
        cnt += ((m & 1u) && v.x >= 0.5f);
        cnt += ((m & 2u) && v.y >= 0.5f);
        cnt += ((m & 4u) && v.z >= 0.5f);
        cnt += ((m & 8u) && v.w >= 0.5f);
    }
    cnt = __reduce_add_sync(0xffffffffu, cnt);

    if (lane == 0) {
        float d = navg[row] - duty[row];               // f32 subtract, as in ref
        float boost = (float)exp((double)d);           // correctly-rounded f32 exp
        g_overlap[row] = boost * (float)cnt;
    }
}

// ---------------------------------------------------------------------------
// Kernel 2: exact top-K (K=656) with jax.lax.top_k tie semantics
// (ties at the threshold resolved by LOWEST index first).
// Single block, 1024 threads, keys staged in 128 KB dynamic shared.
// Radix-select (4 x 8-bit passes), then ordered scan for threshold ties.
// Output: float32 1.0f / 0.0f.
// ---------------------------------------------------------------------------
extern __shared__ uint32_t skeys[];   // N_MC u32 keys = 131072 bytes

__global__ __launch_bounds__(1024) void topk_kernel(float* __restrict__ out)
{
    __shared__ uint32_t s_hist[256];
    __shared__ uint32_t s_prefix;
    __shared__ int      s_rem;
    __shared__ int      s_wincl[32];
    __shared__ int      s_running;

    const int tid  = threadIdx.x;
    const int lane = tid & 31;
    const int wid  = tid >> 5;

    // stage keys (float bits; all values >= 0 so u32 order == float order)
    for (int j = tid; j < N_MC; j += 1024)
        skeys[j] = __float_as_uint(g_overlap[j]);

    if (tid == 0) { s_prefix = 0u; s_rem = K_TOP; s_running = 0; }
    __syncthreads();

    // ---- radix select: find T = K-th largest key ----
    for (int shift = 24; shift >= 0; shift -= 8) {
        if (tid < 256) s_hist[tid] = 0u;
        __syncthreads();
        uint32_t prefix = s_prefix;
        uint64_t phi = (uint64_t)prefix >> (shift + 8);
        for (int j = tid; j < N_MC; j += 1024) {
            uint32_t k = skeys[j];
            if (((uint64_t)k >> (shift + 8)) == phi)
                atomicAdd(&s_hist[(k >> shift) & 255u], 1u);
        }
        __syncthreads();
        if (tid == 0) {
            int rem = s_rem;
            unsigned cum = 0;
            int b = 255;
            for (; b >= 0; --b) {
                cum += s_hist[b];
                if ((int)cum >= rem) break;
            }
            s_rem = rem - (int)(cum - s_hist[b]);
            s_prefix = prefix | ((uint32_t)b << shift);
        }
        __syncthreads();
    }

    const uint32_t T = s_prefix;   // exact K-th largest value (as bits)
    const int      r = s_rem;      // how many ==T entries to take (lowest idx)
    __syncthreads();

    // ---- marking pass with index-ordered scan over ==T entries ----
    for (int base = 0; base < N_MC; base += 1024) {
        int j = base + tid;
        uint32_t k = skeys[j];
        bool eq = (k == T);
        bool gt = (k > T);

        unsigned ball   = __ballot_sync(0xffffffffu, eq);
        int lanepref    = __popc(ball & ((1u << lane) - 1u));
        if (lane == 0) s_wincl[wid] = __popc(ball);
        __syncthreads();

        if (wid == 0) {
            int v = s_wincl[lane];
            #pragma unroll
            for (int off = 1; off < 32; off <<= 1) {
                int u = __shfl_up_sync(0xffffffffu, v, off);
                if (lane >= off) v += u;
            }
            s_wincl[lane] = v;   // inclusive scan of warp totals
        }
        __syncthreads();

        int wpre  = (wid == 0) ? 0 : s_wincl[wid - 1];
        int rank  = s_running + wpre + lanepref;
        out[j] = (gt || (eq && rank < r)) ? 1.0f : 0.0f;

        __syncthreads();
        if (tid == 0) s_running += s_wincl[31];
        __syncthreads();
    }
}

// ---------------------------------------------------------------------------
extern "C" void kernel_launch(void* const* d_in, const int* in_sizes, int n_in,
                              void* d_out, int out_size)
{
    const float* I    = (const float*)d_in[0];
    const float* perm = (const float*)d_in[1];
    const float* duty = (const float*)d_in[2];
    const float* navg = (const float*)d_in[3];
    float* out = (float*)d_out;

    (void)in_sizes; (void)n_in; (void)out_size;

    cudaFuncSetAttribute(topk_kernel,
                         cudaFuncAttributeMaxDynamicSharedMemorySize,
                         N_MC * (int)sizeof(uint32_t));

    pack_mask_kernel<<<N_IN / 256, 256>>>(I);
    overlap_kernel<<<N_MC / 8, 256>>>(perm, duty, navg);
    topk_kernel<<<1, 1024, N_MC * sizeof(uint32_t)>>>(out);
}